// round 3
// baseline (speedup 1.0000x reference)
#include <cuda_runtime.h>
#include <math.h>
#include <stdint.h>

// Problem constants (fixed shapes)
#define NB_   4096        // B*N
#define KK_   48
#define HH_   128
#define FF_   512
#define CHUNK_ 32         // k-rows per streamed weight chunk
__device__ __constant__ float kINV_SCALE = 1.0f/30.0f;
#define EPS_  1e-5f

// Scratch (device globals; no allocation allowed)
__device__ float g_P[NB_*HH_];
__device__ float g_Q[NB_*HH_];
__device__ float g_hV1[NB_*HH_];
__device__ float g_hV2[NB_*HH_];

// ---------------- helpers ----------------
__device__ __forceinline__ float gelu_f(float x){
    return 0.5f*x*(1.0f + erff(x*0.70710678118654752f));
}

__device__ __forceinline__ unsigned long long pack2(float lo, float hi){
    unsigned long long r;
    asm("mov.b64 %0, {%1,%2};" : "=l"(r) : "r"(__float_as_uint(lo)), "r"(__float_as_uint(hi)));
    return r;
}
__device__ __forceinline__ void unpack2(unsigned long long v, float& lo, float& hi){
    unsigned ulo, uhi;
    asm("mov.b64 {%0,%1}, %2;" : "=r"(ulo), "=r"(uhi) : "l"(v));
    lo = __uint_as_float(ulo); hi = __uint_as_float(uhi);
}
__device__ __forceinline__ unsigned long long fma2(unsigned long long a,
                                                   unsigned long long b,
                                                   unsigned long long c){
    unsigned long long d;
    asm("fma.rn.f32x2 %0, %1, %2, %3;" : "=l"(d) : "l"(a), "l"(b), "l"(c));
    return d;
}

__device__ __forceinline__ void cp_async16(void* sdst, const void* gsrc){
    unsigned sa = (unsigned)__cvta_generic_to_shared(sdst);
    asm volatile("cp.async.cg.shared.global [%0], [%1], 16;" :: "r"(sa), "l"(gsrc));
}
#define CP_COMMIT() asm volatile("cp.async.commit_group;")
#define CP_WAIT(n)  asm volatile("cp.async.wait_group %0;" :: "n"(n))

// ---------------- kernel 1: per-node P/Q precompute ----------------
// P = h_V @ W[0:128] + b   (first block of the 3H weight)
// Q = h_V @ W[256:384]     (third block: gathered-neighbor weight)
__global__ void __launch_bounds__(128) prep_pq_kernel(
    const float* __restrict__ hV, const float* __restrict__ W,
    const float* __restrict__ b,  float* __restrict__ P, float* __restrict__ Q)
{
    __shared__ float sh[8][HH_];
    int tid = threadIdx.x;
    int nb = blockIdx.x * 8;
    for (int idx = tid; idx < 8*HH_; idx += 128)
        sh[idx>>7][idx&127] = hV[nb*HH_ + idx];
    __syncthreads();
    int j = tid;
    float accP[8], accQ[8];
    #pragma unroll
    for (int r=0;r<8;r++){ accP[r]=0.f; accQ[r]=0.f; }
    #pragma unroll 4
    for (int i=0;i<HH_;i++){
        float wA = W[i*HH_ + j];
        float wC = W[(256+i)*HH_ + j];
        #pragma unroll
        for (int r=0;r<8;r++){
            float h = sh[r][i];
            accP[r] = fmaf(h, wA, accP[r]);
            accQ[r] = fmaf(h, wC, accQ[r]);
        }
    }
    float bb = b[j];
    #pragma unroll
    for (int r=0;r<8;r++){
        P[(nb+r)*HH_ + j] = accP[r] + bb;
        Q[(nb+r)*HH_ + j] = accQ[r];
    }
}

// ---------------- fused edge-chain kernel ----------------
// smem layout (floats)
#define XS_ 132
#define OFF_WC   0                       // 2 chunk buffers: 2*CHUNK_*HH_ = 8192
#define OFF_X    (2*CHUNK_*HH_)          // 8192
#define OFF_Y    (OFF_X + KK_*XS_)       // 14528
#define OFF_O    (OFF_Y + KK_*XS_)       // 20864
#define OFF_MASK (OFF_O + KK_*HH_)       // 27008
#define OFF_IDX  (OFF_MASK + KK_)        // 27056
#define OFF_RED  (OFF_IDX + KK_)         // 27104
#define SMEM_FLOATS (OFF_RED + 16)       // 27120
#define EDGE_SMEM_BYTES (SMEM_FLOATS*4)  // 108480 B -> 2 CTAs/SM

__device__ __forceinline__ void load_chunk(float* dst, const float* src, int tid){
    // CHUNK_*HH_ = 4096 floats = 1024 x 16B
    for (int i = tid; i < CHUNK_*HH_/4; i += 384)
        cp_async16(dst + i*4, src + i*4);
    CP_COMMIT();
}

// 48x128 @ 128x128 tile GEMM with k-chunked weight streaming.
// Entry contract: chunk0 of Wg already cp.async'd into Wc[0] and committed,
// and it is the SOLE outstanding cp.async group. Exit: zero outstanding groups,
// all threads past final barrier (Ys fully written only after the NEXT sync —
// callers read Ys after the following gemm's first internal sync, or after an
// explicit __syncthreads()).
// mode 0: add per-row Ob[r][c], gelu.  mode 1: add bias4, gelu.  mode 2: add bias4.
__device__ __forceinline__ void gemm_stream(const float* __restrict__ Xs,
    const float* __restrict__ Wg, float* __restrict__ Wc, float* __restrict__ Ys,
    const float* __restrict__ Ob, float4 bias, int mode, int tid)
{
    int cg = tid & 31, rg = tid >> 5;
    int c0 = cg*4, r0 = rg*4;
    unsigned long long acc[4][2];
    #pragma unroll
    for (int i=0;i<4;i++){ acc[i][0]=0ull; acc[i][1]=0ull; }

    #pragma unroll
    for (int c = 0; c < HH_/CHUNK_; c++){
        if (c < HH_/CHUNK_ - 1){
            load_chunk(Wc + ((c+1)&1)*CHUNK_*HH_, Wg + (c+1)*CHUNK_*HH_, tid);
            CP_WAIT(1);                 // chunk c arrived (this thread)
        } else {
            CP_WAIT(0);
        }
        __syncthreads();                // chunk c visible to all; prev compute done
        const float* Wsb = Wc + (c&1)*CHUNK_*HH_;
        #pragma unroll 4
        for (int kk2 = 0; kk2 < CHUNK_; kk2++){
            float4 w = *reinterpret_cast<const float4*>(Wsb + kk2*HH_ + c0);
            unsigned long long wb0 = pack2(w.x, w.y);
            unsigned long long wb1 = pack2(w.z, w.w);
            int kk = c*CHUNK_ + kk2;
            #pragma unroll
            for (int i=0;i<4;i++){
                float x = Xs[(r0+i)*XS_ + kk];
                unsigned long long a = pack2(x, x);
                acc[i][0] = fma2(a, wb0, acc[i][0]);
                acc[i][1] = fma2(a, wb1, acc[i][1]);
            }
        }
        __syncthreads();                // all reads of Wc[c&1] done before reuse
    }

    #pragma unroll
    for (int i=0;i<4;i++){
        float f0,f1,f2,f3;
        unpack2(acc[i][0], f0, f1);
        unpack2(acc[i][1], f2, f3);
        if (mode == 0){
            const float* op = Ob + (r0+i)*HH_ + c0;
            f0+=op[0]; f1+=op[1]; f2+=op[2]; f3+=op[3];
        } else {
            f0+=bias.x; f1+=bias.y; f2+=bias.z; f3+=bias.w;
        }
        if (mode <= 1){
            f0=gelu_f(f0); f1=gelu_f(f1); f2=gelu_f(f2); f3=gelu_f(f3);
        }
        *reinterpret_cast<float4*>(Ys + (r0+i)*XS_ + c0) = make_float4(f0,f1,f2,f3);
    }
}

template<bool NODE>
__global__ void __launch_bounds__(384, 2) edge_chain_kernel(
    const float* __restrict__ hE,
    const int*   __restrict__ Eidx,
    const float* __restrict__ maskA,   // NODE only
    const float* __restrict__ P,
    const float* __restrict__ Q,
    const float* __restrict__ Wb,      // middle 128x128 block of the 3H weight
    const float* __restrict__ W2,
    const float* __restrict__ b2,
    const float* __restrict__ W3,
    const float* __restrict__ b3,
    const float* __restrict__ resid,   // NODE: h_V for residual
    const float* __restrict__ g,
    const float* __restrict__ be,
    float* __restrict__ out)           // NODE: hV1[NB*H] ; else d_out edge section
{
    extern __shared__ float sm[];
    float* Wc    = sm + OFF_WC;
    float* Xb    = sm + OFF_X;
    float* Yb    = sm + OFF_Y;
    float* Ob    = sm + OFF_O;
    float* smask = sm + OFF_MASK;
    int*   sidx  = (int*)(sm + OFF_IDX);
    float* sred  = sm + OFF_RED;

    int tid = threadIdx.x;
    int n = blockIdx.x;            // node index 0..4095
    int bb = n >> 11;              // batch (N = 2048)
    int ebase = n * (KK_*HH_);

    // prefetch chunk0 of W_mid first (overlaps tile prep)
    load_chunk(Wc, Wb, tid);

    if (tid < KK_){
        sidx[tid] = (bb << 11) + Eidx[n*KK_ + tid];
        if (NODE) smask[tid] = maskA[n*KK_ + tid];
    }
    // h_E tile -> Xb
    for (int idx = tid; idx < KK_*HH_; idx += 384){
        int r = idx >> 7, j = idx & 127;
        Xb[r*XS_ + j] = hE[ebase + idx];
    }
    __syncthreads();   // sidx visible
    // O tile: P[n] + Q[gathered neighbor]  (b1 already folded into P)
    const float* Pn = P + n*HH_;
    for (int idx = tid; idx < KK_*HH_; idx += 384){
        int r = idx >> 7, j = idx & 127;
        Ob[idx] = Pn[j] + Q[sidx[r]*HH_ + j];
    }
    // NOTE: Ob writes are ordered before any read by the first sync inside
    // gemm_stream (epilogue reads happen much later).

    float4 bias2 = *reinterpret_cast<const float4*>(b2 + (tid & 31)*4);
    float4 bias3 = *reinterpret_cast<const float4*>(b3 + (tid & 31)*4);

    gemm_stream(Xb, Wb, Wc, Yb, Ob, bias2, 0, tid);   // GEMM1: +O, gelu
    load_chunk(Wc, W2, tid);                          // chunk0 of W2
    gemm_stream(Yb, W2, Wc, Xb, nullptr, bias2, 1, tid); // GEMM2: +b2, gelu
    load_chunk(Wc, W3, tid);                          // chunk0 of W3
    gemm_stream(Xb, W3, Wc, Yb, nullptr, bias3, 2, tid); // GEMM3: +b3
    __syncthreads();   // Yb epilogue visible to all

    if (NODE){
        // masked sum over K, /SCALE, residual, LayerNorm over H (per node)
        float val = 0.f;
        if (tid < HH_){
            float s = 0.f;
            #pragma unroll 4
            for (int r=0;r<KK_;r++) s += smask[r]*Yb[r*XS_ + tid];
            val = resid[n*HH_ + tid] + s*kINV_SCALE;
        }
        float s1 = val, s2 = val*val;
        #pragma unroll
        for (int d=16; d>0; d>>=1){
            s1 += __shfl_xor_sync(0xffffffffu, s1, d);
            s2 += __shfl_xor_sync(0xffffffffu, s2, d);
        }
        if (tid < HH_ && (tid & 31)==0){ sred[tid>>5] = s1; sred[4 + (tid>>5)] = s2; }
        __syncthreads();
        if (tid < HH_){
            float t1 = sred[0]+sred[1]+sred[2]+sred[3];
            float t2 = sred[4]+sred[5]+sred[6]+sred[7];
            float m  = t1 * (1.f/128.f);
            float var= t2 * (1.f/128.f) - m*m;
            float rs = rsqrtf(var + EPS_);
            out[n*HH_ + tid] = (val - m)*rs*g[tid] + be[tid];
        }
    } else {
        // per-edge-row LayerNorm of (h_E + msg); 48 rows x 8 threads
        int r = tid >> 3, s = tid & 7;
        int rowg = ebase + r*HH_;
        float v[16];
        float s1=0.f, s2=0.f;
        #pragma unroll
        for (int t=0;t<16;t++){
            int j = s + t*8;
            float x = hE[rowg + j] + Yb[r*XS_ + j];
            v[t] = x; s1 += x; s2 += x*x;
        }
        #pragma unroll
        for (int d=4; d>0; d>>=1){  // reduce within 8-lane groups
            s1 += __shfl_xor_sync(0xffffffffu, s1, d);
            s2 += __shfl_xor_sync(0xffffffffu, s2, d);
        }
        float m  = s1*(1.f/128.f);
        float var= s2*(1.f/128.f) - m*m;
        float rs = rsqrtf(var + EPS_);
        #pragma unroll
        for (int t=0;t<16;t++){
            int j = s + t*8;
            out[rowg + j] = (v[t]-m)*rs*g[j] + be[j];
        }
    }
}

// ---------------- FFN + LN2 + mask_V (8 nodes per CTA) ----------------
__global__ void __launch_bounds__(256) ffn_kernel(
    const float* __restrict__ hV1,
    const float* __restrict__ Wi, const float* __restrict__ bi,
    const float* __restrict__ Wo, const float* __restrict__ bo,
    const float* __restrict__ g2, const float* __restrict__ be2,
    const float* __restrict__ maskV,
    float* __restrict__ hV2, float* __restrict__ outV)
{
    __shared__ float sh[8][HH_];
    __shared__ float st[8][FF_ + 4];
    __shared__ float sp[2][8][HH_];
    int tid = threadIdx.x;
    int nb = blockIdx.x * 8;
    for (int idx = tid; idx < 8*HH_; idx += 256)
        sh[idx>>7][idx&127] = hV1[nb*HH_ + idx];
    __syncthreads();
    // stage 1: t = gelu(h @ Wi + bi)
    for (int p = 0; p < 2; p++){
        int jj = p*256 + tid;
        float acc[8];
        float b0 = bi[jj];
        #pragma unroll
        for (int r=0;r<8;r++) acc[r] = b0;
        for (int i=0;i<HH_;i+=4){
            float w0 = Wi[(i+0)*FF_ + jj];
            float w1 = Wi[(i+1)*FF_ + jj];
            float w2 = Wi[(i+2)*FF_ + jj];
            float w3 = Wi[(i+3)*FF_ + jj];
            #pragma unroll
            for (int r=0;r<8;r++){
                float4 h4 = *reinterpret_cast<const float4*>(&sh[r][i]);
                acc[r] = fmaf(h4.x,w0, fmaf(h4.y,w1, fmaf(h4.z,w2, fmaf(h4.w,w3, acc[r]))));
            }
        }
        #pragma unroll
        for (int r=0;r<8;r++) st[r][jj] = gelu_f(acc[r]);
    }
    __syncthreads();
    // stage 2: dh = t @ Wo (split i-range across 2 halves)
    {
        int o = tid & 127, half = tid >> 7;
        float acc[8];
        #pragma unroll
        for (int r=0;r<8;r++) acc[r]=0.f;
        int i0 = half*256;
        for (int i=i0; i<i0+256; i+=4){
            float w0 = Wo[(i+0)*HH_ + o];
            float w1 = Wo[(i+1)*HH_ + o];
            float w2 = Wo[(i+2)*HH_ + o];
            float w3 = Wo[(i+3)*HH_ + o];
            #pragma unroll
            for (int r=0;r<8;r++){
                float4 t4 = *reinterpret_cast<const float4*>(&st[r][i]);
                acc[r] = fmaf(t4.x,w0, fmaf(t4.y,w1, fmaf(t4.z,w2, fmaf(t4.w,w3, acc[r]))));
            }
        }
        #pragma unroll
        for (int r=0;r<8;r++) sp[half][r][o] = acc[r];
    }
    __syncthreads();
    // LN over H per row; one warp per row
    int r = tid >> 5, lane = tid & 31;
    float v[4]; float s1=0.f, s2=0.f;
    #pragma unroll
    for (int q=0;q<4;q++){
        int oo = lane*4 + q;
        float x = sh[r][oo] + sp[0][r][oo] + sp[1][r][oo] + bo[oo];
        v[q]=x; s1+=x; s2+=x*x;
    }
    #pragma unroll
    for (int d=16; d>0; d>>=1){
        s1 += __shfl_xor_sync(0xffffffffu, s1, d);
        s2 += __shfl_xor_sync(0xffffffffu, s2, d);
    }
    float m  = s1*(1.f/128.f);
    float var= s2*(1.f/128.f) - m*m;
    float rs = rsqrtf(var + EPS_);
    float mv = maskV[nb + r];
    #pragma unroll
    for (int q=0;q<4;q++){
        int oo = lane*4 + q;
        float o1 = ((v[q]-m)*rs*g2[oo] + be2[oo]) * mv;
        hV2 [(nb+r)*HH_ + oo] = o1;
        outV[(nb+r)*HH_ + oo] = o1;
    }
}

// ---------------- launch ----------------
extern "C" void kernel_launch(void* const* d_in, const int* in_sizes, int n_in,
                              void* d_out, int out_size)
{
    (void)in_sizes; (void)n_in; (void)out_size;
    const float* hV    = (const float*)d_in[0];
    const float* hE    = (const float*)d_in[1];
    const int*   Eidx  = (const int*)  d_in[2];
    const float* maskV = (const float*)d_in[3];
    const float* maskA = (const float*)d_in[4];
    const float* W1  = (const float*)d_in[5];
    const float* b1  = (const float*)d_in[6];
    const float* W2  = (const float*)d_in[7];
    const float* b2  = (const float*)d_in[8];
    const float* W3  = (const float*)d_in[9];
    const float* b3  = (const float*)d_in[10];
    const float* W11 = (const float*)d_in[11];
    const float* b11 = (const float*)d_in[12];
    const float* W12 = (const float*)d_in[13];
    const float* b12 = (const float*)d_in[14];
    const float* W13 = (const float*)d_in[15];
    const float* b13 = (const float*)d_in[16];
    const float* Wi  = (const float*)d_in[17];
    const float* bi  = (const float*)d_in[18];
    const float* Wo  = (const float*)d_in[19];
    const float* bo  = (const float*)d_in[20];
    const float* g1  = (const float*)d_in[21];
    const float* be1 = (const float*)d_in[22];
    const float* g2  = (const float*)d_in[23];
    const float* be2 = (const float*)d_in[24];
    const float* g3  = (const float*)d_in[25];
    const float* be3 = (const float*)d_in[26];

    float* outV = (float*)d_out;
    float* outE = outV + (size_t)NB_*HH_;

    float *P, *Q, *hV1, *hV2;
    cudaGetSymbolAddress((void**)&P,   g_P);
    cudaGetSymbolAddress((void**)&Q,   g_Q);
    cudaGetSymbolAddress((void**)&hV1, g_hV1);
    cudaGetSymbolAddress((void**)&hV2, g_hV2);

    cudaFuncSetAttribute(edge_chain_kernel<true>,
                         cudaFuncAttributeMaxDynamicSharedMemorySize, EDGE_SMEM_BYTES);
    cudaFuncSetAttribute(edge_chain_kernel<false>,
                         cudaFuncAttributeMaxDynamicSharedMemorySize, EDGE_SMEM_BYTES);

    // --- node update ---
    prep_pq_kernel<<<NB_/8, 128>>>(hV, W1, b1, P, Q);
    edge_chain_kernel<true><<<NB_, 384, EDGE_SMEM_BYTES>>>(
        hE, Eidx, maskA, P, Q, W1 + HH_*HH_, W2, b2, W3, b3, hV, g1, be1, hV1);
    ffn_kernel<<<NB_/8, 256>>>(hV1, Wi, bi, Wo, bo, g2, be2, maskV, hV2, outV);
    // --- edge update ---
    prep_pq_kernel<<<NB_/8, 128>>>(hV2, W11, b11, P, Q);
    edge_chain_kernel<false><<<NB_, 384, EDGE_SMEM_BYTES>>>(
        hE, Eidx, nullptr, P, Q, W11 + HH_*HH_, W12, b12, W13, b13, nullptr, g3, be3, outE);
}